// round 11
// baseline (speedup 1.0000x reference)
#include <cuda_runtime.h>
#include <cuda_fp16.h>
#include <stdint.h>
#include <math.h>

// EBM Langevin MCMC via mma.sync HMMA. R10 = R9 + software-pipelined B-fragment
// double buffering in do_gemm (prefetch iteration i+1's ldmatrix while issuing
// iteration i's 6 MMAs) -> hides LDSM latency that held tensor pipe at 53%.
// Persistent grid (152 CTAs), s2/s3 in small __device__ scratch, VOLATILE
// ldmatrix (pins weight loads in-loop; non-volatile caused 1.6GB local
// demotion in R7/R8), zero-C first-kk MMA.
// Weights: one SMEM tile per layer, F[a][b] = W[b][a] fp16 hi+lo, pad-136 rows.
//   fwd GEMM:  B[k][n] = F[n][k]  -> ldmatrix (non-trans)
//   bwd GEMM:  B[j][n] = F[j][n]  -> ldmatrix.trans  (same tile)
// 3-pass per GEMM: Ahi*Bhi + Alo*Bhi + Ahi*Blo => ~fp32 accuracy.

#define H 128
#define NT 256
#define CPB 128
#define SP 136                 // padded row stride (halves); 272 bytes
#define TILE 34816             // 128*272 bytes
#define NBLK 152               // persistent grid size (>= SM count)

#define OFF_WHI 0
#define OFF_WLO (3*TILE)       // 104448
#define OFF_W1  208896
#define OFF_B1  209920
#define OFF_B2  210432
#define OFF_B3  210944
#define OFF_B4  211456
#define OFF_W5  211968
#define SMEM_BYTES 212480

// scratch for s2/s3: [block][64 slots][256 threads] uint2 = ~20 MB total
__device__ uint2 g_sscr[(size_t)NBLK * 64 * NT];

// non-volatile: pure register computation, lets compiler interleave chains
#define MMA4(D, A, b0, b1) asm( \
  "mma.sync.aligned.m16n8k16.row.col.f32.f16.f16.f32 " \
  "{%0,%1,%2,%3},{%4,%5,%6,%7},{%8,%9},{%0,%1,%2,%3};" \
  : "+f"((D)[0]),"+f"((D)[1]),"+f"((D)[2]),"+f"((D)[3]) \
  : "r"((A)[0]),"r"((A)[1]),"r"((A)[2]),"r"((A)[3]),"r"(b0),"r"(b1))

// write-only D with C = 0 (no accumulator init needed)
#define MMA4Z(D, A, b0, b1) asm( \
  "mma.sync.aligned.m16n8k16.row.col.f32.f16.f16.f32 " \
  "{%0,%1,%2,%3},{%4,%5,%6,%7},{%8,%9},{%10,%10,%10,%10};" \
  : "=f"((D)[0]),"=f"((D)[1]),"=f"((D)[2]),"=f"((D)[3]) \
  : "r"((A)[0]),"r"((A)[1]),"r"((A)[2]),"r"((A)[3]),"r"(b0),"r"(b1),"f"(0.0f))

// VOLATILE: keeps ldmatrix inside the step loop (prevents invariant hoisting
// of the whole weight tile into local memory)
#define LDSM4(r0,r1,r2,r3,a) asm volatile( \
  "ldmatrix.sync.aligned.m8n8.x4.shared.b16 {%0,%1,%2,%3}, [%4];" \
  : "=r"(r0),"=r"(r1),"=r"(r2),"=r"(r3) : "r"(a))

#define LDSM4T(r0,r1,r2,r3,a) asm volatile( \
  "ldmatrix.sync.aligned.m8n8.x4.trans.shared.b16 {%0,%1,%2,%3}, [%4];" \
  : "=r"(r0),"=r"(r1),"=r"(r2),"=r"(r3) : "r"(a))

__device__ __forceinline__ uint32_t smem_u32(const void* p) {
    uint32_t a;
    asm("{ .reg .u64 t; cvta.to.shared.u64 t, %1; cvt.u32.u64 %0, t; }" : "=r"(a) : "l"(p));
    return a;
}
__device__ __forceinline__ void silu2(float z, float* h, float* sp) {
    float sg = __fdividef(1.0f, 1.0f + __expf(-z));
    *h = z * sg;
    *sp = sg * (1.0f + z * (1.0f - sg));
}
__device__ __forceinline__ float silu_d(float z) {
    float sg = __fdividef(1.0f, 1.0f + __expf(-z));
    return sg * (1.0f + z * (1.0f - sg));
}
__device__ __forceinline__ uint32_t pack_hl(float v0, float v1, uint32_t* lo) {
    __half h0 = __float2half_rn(v0), h1 = __float2half_rn(v1);
    __half l0 = __float2half_rn(v0 - __half2float(h0));
    __half l1 = __float2half_rn(v1 - __half2float(h1));
    __half2 hp = __halves2half2(h0, h1), lp = __halves2half2(l0, l1);
    *lo = *reinterpret_cast<uint32_t*>(&lp);
    return *reinterpret_cast<uint32_t*>(&hp);
}
__device__ __forceinline__ uint2 pack_hl2(float v0, float v1) {
    uint2 r;
    r.x = pack_hl(v0, v1, &r.y);
    return r;
}
__device__ __forceinline__ float2 unpack2(uint32_t u) {
    return __half22float2(*reinterpret_cast<__half2*>(&u));
}
__device__ __forceinline__ float2 unpack_hl(uint32_t hi, uint32_t lo) {
    float2 a = unpack2(hi), b = unpack2(lo);
    return make_float2(a.x + b.x, a.y + b.y);
}

// one iteration's B fragments: [0..3] = hi, [4..7] = lo
template<bool TR>
__device__ __forceinline__ void ldB(uint32_t* buf, uint32_t baseHI, uint32_t baseLO, int i) {
    int kk = i >> 3, ntp = i & 7;
    uint32_t off = TR ? (uint32_t)(kk*4352 + ntp*32) : (uint32_t)(ntp*4352 + kk*32);
    if (TR) {
        LDSM4T(buf[0], buf[1], buf[2], buf[3], baseHI + off);
        LDSM4T(buf[4], buf[5], buf[6], buf[7], baseLO + off);
    } else {
        LDSM4 (buf[0], buf[1], buf[2], buf[3], baseHI + off);
        LDSM4 (buf[4], buf[5], buf[6], buf[7], baseLO + off);
    }
}

// fwd (TR=false): addr = base + ntp*4352 + kk*32 ; bwd (TR=true): base + kk*4352 + ntp*32
// Software-pipelined: prefetch B for iteration i+1, then issue the 6 MMAs for i.
template<bool TR>
__device__ __forceinline__ void do_gemm(float* d, const uint32_t* aHI, const uint32_t* aLO,
                                        uint32_t baseHI, uint32_t baseLO)
{
    uint32_t bufA[8], bufB[8];
    ldB<TR>(bufA, baseHI, baseLO, 0);
    #pragma unroll
    for (int i = 0; i < 64; ++i) {
        uint32_t* cur = (i & 1) ? bufB : bufA;
        uint32_t* nxt = (i & 1) ? bufA : bufB;
        if (i < 63) ldB<TR>(nxt, baseHI, baseLO, i + 1);
        const int kk = i >> 3, ntp = i & 7;
        const uint32_t* ah = aHI + 4*kk;
        const uint32_t* al = aLO + 4*kk;
        float* d0 = d + 8*ntp;
        float* d1 = d0 + 4;
        if (kk == 0) {
            MMA4Z(d0, ah, cur[0], cur[1]);
            MMA4Z(d1, ah, cur[2], cur[3]);
        } else {
            MMA4(d0, ah, cur[0], cur[1]);
            MMA4(d1, ah, cur[2], cur[3]);
        }
        MMA4(d0, al, cur[0], cur[1]);
        MMA4(d1, al, cur[2], cur[3]);
        MMA4(d0, ah, cur[4], cur[5]);
        MMA4(d1, ah, cur[6], cur[7]);
    }
}

// fwd epilogue: silu -> A hi/lo regs; silu' hi/lo pairs -> global scratch (coalesced)
__device__ __forceinline__ void epi_fwd(const float* d, const float* bias, int tg,
                                        uint32_t* aHI, uint32_t* aLO, uint2* sp)
{
    #pragma unroll
    for (int j = 0; j < 16; ++j) {
        int c0 = 8*j + 2*tg;
        float b0 = bias[c0], b1v = bias[c0+1];
        float h0,s0,h1,s1v,h2,s2v,h3,s3v;
        silu2(d[4*j]   + b0,  &h0, &s0);
        silu2(d[4*j+1] + b1v, &h1, &s1v);
        silu2(d[4*j+2] + b0,  &h2, &s2v);
        silu2(d[4*j+3] + b1v, &h3, &s3v);
        aHI[2*j]   = pack_hl(h0, h1, &aLO[2*j]);
        aHI[2*j+1] = pack_hl(h2, h3, &aLO[2*j+1]);
        sp[(2*j)*NT]   = pack_hl2(s0,  s1v);
        sp[(2*j+1)*NT] = pack_hl2(s2v, s3v);
    }
}
__device__ __forceinline__ void epi_u4(const float* d, const float* b4s, const float* w5s,
                                       int tg, uint32_t* aHI, uint32_t* aLO)
{
    #pragma unroll
    for (int j = 0; j < 16; ++j) {
        int c0 = 8*j + 2*tg;
        float b0 = b4s[c0], b1v = b4s[c0+1];
        float w0 = w5s[c0], w1v = w5s[c0+1];
        float s0 = silu_d(d[4*j]   + b0);
        float s1v = silu_d(d[4*j+1] + b1v);
        float s2v = silu_d(d[4*j+2] + b0);
        float s3v = silu_d(d[4*j+3] + b1v);
        aHI[2*j]   = pack_hl(w0*s0,  w1v*s1v, &aLO[2*j]);
        aHI[2*j+1] = pack_hl(w0*s2v, w1v*s3v, &aLO[2*j+1]);
    }
}
// bwd epilogue: u = D * s (s from global scratch) -> A hi/lo
__device__ __forceinline__ void epi_bwd(const float* d, const uint2* sp,
                                        uint32_t* aHI, uint32_t* aLO)
{
    #pragma unroll
    for (int j = 0; j < 16; ++j) {
        uint2 pa = sp[(2*j)*NT];
        uint2 pb = sp[(2*j+1)*NT];
        float2 sa = unpack_hl(pa.x, pa.y);
        float2 sb = unpack_hl(pb.x, pb.y);
        aHI[2*j]   = pack_hl(d[4*j]*sa.x,   d[4*j+1]*sa.y, &aLO[2*j]);
        aHI[2*j+1] = pack_hl(d[4*j+2]*sb.x, d[4*j+3]*sb.y, &aLO[2*j+1]);
    }
}

__global__ __launch_bounds__(NT, 1)
void ebm_hmma_kernel(
    const float* __restrict__ x0,
    const float* __restrict__ w1, const float* __restrict__ b1,
    const float* __restrict__ w2, const float* __restrict__ b2,
    const float* __restrict__ w3, const float* __restrict__ b3,
    const float* __restrict__ w4, const float* __restrict__ b4,
    const float* __restrict__ w5,
    const float* __restrict__ noise,
    float* __restrict__ out, int nChains, int nSteps)
{
    extern __shared__ char sm[];
    float* w1s  = (float*)(sm + OFF_W1);
    float* b1s  = (float*)(sm + OFF_B1);
    float* b2s  = (float*)(sm + OFF_B2);
    float* b3s  = (float*)(sm + OFF_B3);
    float* b4s  = (float*)(sm + OFF_B4);
    float* w5s  = (float*)(sm + OFF_W5);
    const uint32_t sb = smem_u32(sm);

    const int tid  = threadIdx.x;
    const int lane = tid & 31, warp = tid >> 5;
    const int tg   = lane & 3, g = lane >> 2;
    const int r0   = warp*16 + g, r1 = r0 + 8;

    // per-thread scratch pointers: s2 at slots 0..31, s3 at slots 32..63 (per block)
    uint2* s2p = g_sscr + ((size_t)blockIdx.x * 64) * NT + tid;
    uint2* s3p = s2p + (size_t)32 * NT;

    // per-lane ldmatrix offsets (bytes)
    const uint32_t loF = (uint32_t)(((lane&7) + ((lane>>4)&1)*8)*272 + ((lane>>3)&1)*16);
    const uint32_t loB = (uint32_t)(((lane&7) + ((lane>>3)&1)*8)*272 + ((lane>>4)&1)*16);

    // ---- load weights once per CTA: F[a][b] = W[b][a], hi + lo fp16 ----
    {
        const float* wsrc[3] = {w2, w3, w4};
        #pragma unroll
        for (int m = 0; m < 3; ++m) {
            char* hi = sm + OFF_WHI + m*TILE;
            char* lo = sm + OFF_WLO + m*TILE;
            const float* w = wsrc[m];
            for (int idx = tid; idx < H*H; idx += NT) {
                int k = idx >> 7, j = idx & 127;      // w[k][j]
                float v = w[idx];
                __half h = __float2half_rn(v);
                __half l = __float2half_rn(v - __half2float(h));
                int o = (j*SP + k)*2;                 // F[j][k]
                *(__half*)(hi + o) = h;
                *(__half*)(lo + o) = l;
            }
        }
        if (tid < 2*H) w1s[tid] = w1[tid];
        if (tid < H) {
            b1s[tid] = b1[tid]; b2s[tid] = b2[tid]; b3s[tid] = b3[tid];
            b4s[tid] = b4[tid]; w5s[tid] = w5[tid];
        }
    }
    __syncthreads();

    const uint32_t t0h = sb + OFF_WHI + 0*TILE, t0l = sb + OFF_WLO + 0*TILE;
    const uint32_t t1h = sb + OFF_WHI + 1*TILE, t1l = sb + OFF_WLO + 1*TILE;
    const uint32_t t2h = sb + OFF_WHI + 2*TILE, t2l = sb + OFF_WLO + 2*TILE;

    const float2* nz2 = (const float2*)noise;
    const int nTiles = (nChains + CPB - 1) / CPB;

    // ---- persistent loop over chain tiles ----
    for (int tile = blockIdx.x; tile < nTiles; tile += gridDim.x) {
        const int ch0 = tile*CPB + r0, ch1 = tile*CPB + r1;
        float2 xv0 = (ch0 < nChains) ? ((const float2*)x0)[ch0] : make_float2(0.f, 0.f);
        float2 xv1 = (ch1 < nChains) ? ((const float2*)x0)[ch1] : make_float2(0.f, 0.f);

        uint32_t aHI[32], aLO[32];
        float d[64];

        for (int t = 0; t < nSteps; ++t) {
            const float eps = 10.0f * (1.0f - (float)t / (float)nSteps);

            // ---- layer 1 (SIMT): h1 = silu(b1 + x.w1); s1 recomputed later ----
            #pragma unroll
            for (int j = 0; j < 16; ++j) {
                int c0 = 8*j + 2*tg;
                float wa = w1s[c0], wb = w1s[c0+1], wc = w1s[128+c0], wd = w1s[129+c0];
                float ba = b1s[c0], bb = b1s[c0+1];
                float h0,sa0,h1v,sa1,h2,sb0,h3,sb1;
                silu2(ba + xv0.x*wa + xv0.y*wc, &h0,  &sa0);
                silu2(bb + xv0.x*wb + xv0.y*wd, &h1v, &sa1);
                silu2(ba + xv1.x*wa + xv1.y*wc, &h2,  &sb0);
                silu2(bb + xv1.x*wb + xv1.y*wd, &h3,  &sb1);
                aHI[2*j]   = pack_hl(h0, h1v, &aLO[2*j]);
                aHI[2*j+1] = pack_hl(h2, h3,  &aLO[2*j+1]);
            }

            do_gemm<false>(d, aHI, aLO, t0h + loF, t0l + loF);   // z2
            epi_fwd(d, b2s, tg, aHI, aLO, s2p);
            do_gemm<false>(d, aHI, aLO, t1h + loF, t1l + loF);   // z3
            epi_fwd(d, b3s, tg, aHI, aLO, s3p);
            do_gemm<false>(d, aHI, aLO, t2h + loF, t2l + loF);   // z4
            epi_u4(d, b4s, w5s, tg, aHI, aLO);                   // u4 = w5*silu'(z4)
            do_gemm<true>(d, aHI, aLO, t2h + loB, t2l + loB);    // u3 raw
            epi_bwd(d, s3p, aHI, aLO);
            do_gemm<true>(d, aHI, aLO, t1h + loB, t1l + loB);    // u2 raw
            epi_bwd(d, s2p, aHI, aLO);
            do_gemm<true>(d, aHI, aLO, t0h + loB, t0l + loB);    // u1 raw

            // ---- final: recompute s1; u1 = D*s1; g[dim] = sum_k u1[k]*w1[dim][k] ----
            float a00 = 0.f, a01 = 0.f, a10 = 0.f, a11 = 0.f;
            #pragma unroll
            for (int j = 0; j < 16; ++j) {
                int c0 = 8*j + 2*tg;
                float wa = w1s[c0], wb = w1s[c0+1], wc = w1s[128+c0], wd = w1s[129+c0];
                float ba = b1s[c0], bb = b1s[c0+1];
                float sa0 = silu_d(ba + xv0.x*wa + xv0.y*wc);
                float sa1 = silu_d(bb + xv0.x*wb + xv0.y*wd);
                float sb0 = silu_d(ba + xv1.x*wa + xv1.y*wc);
                float sb1 = silu_d(bb + xv1.x*wb + xv1.y*wd);
                float u0 = d[4*j]*sa0,   u1v = d[4*j+1]*sa1;
                float u2 = d[4*j+2]*sb0, u3  = d[4*j+3]*sb1;
                a00 += u0*wa + u1v*wb;  a01 += u0*wc + u1v*wd;
                a10 += u2*wa + u3*wb;   a11 += u2*wc + u3*wd;
            }
            #pragma unroll
            for (int m = 1; m <= 2; m <<= 1) {
                a00 += __shfl_xor_sync(0xffffffffu, a00, m);
                a01 += __shfl_xor_sync(0xffffffffu, a01, m);
                a10 += __shfl_xor_sync(0xffffffffu, a10, m);
                a11 += __shfl_xor_sync(0xffffffffu, a11, m);
            }

            // ---- x update, all 4 lanes redundantly (identical, deterministic) ----
            {
                float g0 = fminf(fmaxf(a00, -0.03f), 0.03f);
                float g1 = fminf(fmaxf(a01, -0.03f), 0.03f);
                float g2 = fminf(fmaxf(a10, -0.03f), 0.03f);
                float g3 = fminf(fmaxf(a11, -0.03f), 0.03f);
                float sq = sqrtf(2.0f * eps);
                float2 nzA = (ch0 < nChains) ? nz2[(size_t)t*nChains + ch0] : make_float2(0.f, 0.f);
                float2 nzB = (ch1 < nChains) ? nz2[(size_t)t*nChains + ch1] : make_float2(0.f, 0.f);
                xv0.x = fminf(fmaxf(xv0.x + sq*nzA.x*0.005f + eps*g0, -2.43f), 3.05f);
                xv0.y = fminf(fmaxf(xv0.y + sq*nzA.y*0.005f + eps*g1, -2.43f), 3.05f);
                xv1.x = fminf(fmaxf(xv1.x + sq*nzB.x*0.005f + eps*g2, -2.43f), 3.05f);
                xv1.y = fminf(fmaxf(xv1.y + sq*nzB.y*0.005f + eps*g3, -2.43f), 3.05f);
            }
        }

        if (tg == 0) {
            if (ch0 < nChains) ((float2*)out)[ch0] = xv0;
            if (ch1 < nChains) ((float2*)out)[ch1] = xv1;
        }
    }
}

extern "C" void kernel_launch(void* const* d_in, const int* in_sizes, int n_in,
                              void* d_out, int out_size) {
    const float* x0 = (const float*)d_in[0];
    const float* w1 = (const float*)d_in[1];
    const float* b1 = (const float*)d_in[2];
    const float* w2 = (const float*)d_in[3];
    const float* b2 = (const float*)d_in[4];
    const float* w3 = (const float*)d_in[5];
    const float* b3 = (const float*)d_in[6];
    const float* w4 = (const float*)d_in[7];
    const float* b4 = (const float*)d_in[8];
    const float* w5 = (const float*)d_in[9];
    // d_in[10] = b5: constant offset, no effect on gradient
    const float* noise = (const float*)d_in[11];
    float* out = (float*)d_out;

    int nChains = in_sizes[0] / 2;
    int nSteps  = in_sizes[11] / in_sizes[0];

    cudaFuncSetAttribute(ebm_hmma_kernel, cudaFuncAttributeMaxDynamicSharedMemorySize, SMEM_BYTES);
    int nTiles = (nChains + CPB - 1) / CPB;
    int grid = (nTiles < NBLK) ? nTiles : NBLK;
    ebm_hmma_kernel<<<grid, NT, SMEM_BYTES>>>(x0, w1, b1, w2, b2, w3, b3, w4, b4, w5,
                                              noise, out, nChains, nSteps);
}

// round 12
// speedup vs baseline: 1.4926x; 1.4926x over previous
#include <cuda_runtime.h>
#include <cuda_fp16.h>
#include <stdint.h>
#include <math.h>

// EBM Langevin MCMC via mma.sync HMMA. R11 = R9 (best: 14198us) + anti-phase
// warp skew: warps 4-7 (partners of 0-3 on the same SMSP) run 3 dummy GEMMs
// once at start, breaking the arbiter phase-lock so each warp's MUFU/FMA
// epilogue overlaps its SMSP partner's MMA phase.
// R10 lesson: do NOT touch the GEMM loop's register footprint (255-reg cap).
// Persistent grid (152 CTAs), s2/s3 in small __device__ scratch, VOLATILE
// ldmatrix (pins weight loads in-loop; non-volatile -> 1.6GB local demotion).
// Weights: one SMEM tile per layer, F[a][b] = W[b][a] fp16 hi+lo, pad-136 rows.
//   fwd GEMM:  B[k][n] = F[n][k]  -> ldmatrix (non-trans)
//   bwd GEMM:  B[j][n] = F[j][n]  -> ldmatrix.trans  (same tile)
// 3-pass per GEMM: Ahi*Bhi + Alo*Bhi + Ahi*Blo => ~fp32 accuracy.

#define H 128
#define NT 256
#define CPB 128
#define SP 136                 // padded row stride (halves); 272 bytes
#define TILE 34816             // 128*272 bytes
#define NBLK 152               // persistent grid size (>= SM count)

#define OFF_WHI 0
#define OFF_WLO (3*TILE)       // 104448
#define OFF_W1  208896
#define OFF_B1  209920
#define OFF_B2  210432
#define OFF_B3  210944
#define OFF_B4  211456
#define OFF_W5  211968
#define SMEM_BYTES 212480

// scratch for s2/s3: [block][64 slots][256 threads] uint2 = ~20 MB total
__device__ uint2 g_sscr[(size_t)NBLK * 64 * NT];

// non-volatile: pure register computation, lets compiler interleave chains
#define MMA4(D, A, b0, b1) asm( \
  "mma.sync.aligned.m16n8k16.row.col.f32.f16.f16.f32 " \
  "{%0,%1,%2,%3},{%4,%5,%6,%7},{%8,%9},{%0,%1,%2,%3};" \
  : "+f"((D)[0]),"+f"((D)[1]),"+f"((D)[2]),"+f"((D)[3]) \
  : "r"((A)[0]),"r"((A)[1]),"r"((A)[2]),"r"((A)[3]),"r"(b0),"r"(b1))

// write-only D with C = 0 (no accumulator init needed)
#define MMA4Z(D, A, b0, b1) asm( \
  "mma.sync.aligned.m16n8k16.row.col.f32.f16.f16.f32 " \
  "{%0,%1,%2,%3},{%4,%5,%6,%7},{%8,%9},{%10,%10,%10,%10};" \
  : "=f"((D)[0]),"=f"((D)[1]),"=f"((D)[2]),"=f"((D)[3]) \
  : "r"((A)[0]),"r"((A)[1]),"r"((A)[2]),"r"((A)[3]),"r"(b0),"r"(b1),"f"(0.0f))

// VOLATILE: keeps ldmatrix inside the step loop (prevents invariant hoisting
// of the whole weight tile into local memory)
#define LDSM4(r0,r1,r2,r3,a) asm volatile( \
  "ldmatrix.sync.aligned.m8n8.x4.shared.b16 {%0,%1,%2,%3}, [%4];" \
  : "=r"(r0),"=r"(r1),"=r"(r2),"=r"(r3) : "r"(a))

#define LDSM4T(r0,r1,r2,r3,a) asm volatile( \
  "ldmatrix.sync.aligned.m8n8.x4.trans.shared.b16 {%0,%1,%2,%3}, [%4];" \
  : "=r"(r0),"=r"(r1),"=r"(r2),"=r"(r3) : "r"(a))

__device__ __forceinline__ uint32_t smem_u32(const void* p) {
    uint32_t a;
    asm("{ .reg .u64 t; cvta.to.shared.u64 t, %1; cvt.u32.u64 %0, t; }" : "=r"(a) : "l"(p));
    return a;
}
__device__ __forceinline__ void silu2(float z, float* h, float* sp) {
    float sg = __fdividef(1.0f, 1.0f + __expf(-z));
    *h = z * sg;
    *sp = sg * (1.0f + z * (1.0f - sg));
}
__device__ __forceinline__ float silu_d(float z) {
    float sg = __fdividef(1.0f, 1.0f + __expf(-z));
    return sg * (1.0f + z * (1.0f - sg));
}
__device__ __forceinline__ uint32_t pack_hl(float v0, float v1, uint32_t* lo) {
    __half h0 = __float2half_rn(v0), h1 = __float2half_rn(v1);
    __half l0 = __float2half_rn(v0 - __half2float(h0));
    __half l1 = __float2half_rn(v1 - __half2float(h1));
    __half2 hp = __halves2half2(h0, h1), lp = __halves2half2(l0, l1);
    *lo = *reinterpret_cast<uint32_t*>(&lp);
    return *reinterpret_cast<uint32_t*>(&hp);
}
__device__ __forceinline__ uint2 pack_hl2(float v0, float v1) {
    uint2 r;
    r.x = pack_hl(v0, v1, &r.y);
    return r;
}
__device__ __forceinline__ float2 unpack2(uint32_t u) {
    return __half22float2(*reinterpret_cast<__half2*>(&u));
}
__device__ __forceinline__ float2 unpack_hl(uint32_t hi, uint32_t lo) {
    float2 a = unpack2(hi), b = unpack2(lo);
    return make_float2(a.x + b.x, a.y + b.y);
}

// fwd (TR=false): addr = base + ntp*4352 + kk*32 ; bwd (TR=true): base + kk*4352 + ntp*32
template<bool TR>
__device__ __forceinline__ void do_gemm(float* d, const uint32_t* aHI, const uint32_t* aLO,
                                        uint32_t baseHI, uint32_t baseLO)
{
    // kk = 0: zero-C MMAs initialize d
    {
        const uint32_t* ah = aHI;
        const uint32_t* al = aLO;
        #pragma unroll
        for (int ntp = 0; ntp < 8; ++ntp) {
            uint32_t off = TR ? (uint32_t)(ntp*32) : (uint32_t)(ntp*4352);
            uint32_t bh0,bh1,bh2,bh3, bl0,bl1,bl2,bl3;
            if (TR) { LDSM4T(bh0,bh1,bh2,bh3, baseHI + off); LDSM4T(bl0,bl1,bl2,bl3, baseLO + off); }
            else    { LDSM4 (bh0,bh1,bh2,bh3, baseHI + off); LDSM4 (bl0,bl1,bl2,bl3, baseLO + off); }
            float* d0 = d + 8*ntp;
            float* d1 = d0 + 4;
            MMA4Z(d0, ah, bh0, bh1);
            MMA4Z(d1, ah, bh2, bh3);
            MMA4(d0, al, bh0, bh1);
            MMA4(d1, al, bh2, bh3);
            MMA4(d0, ah, bl0, bl1);
            MMA4(d1, ah, bl2, bl3);
        }
    }
    #pragma unroll
    for (int kk = 1; kk < 8; ++kk) {
        const uint32_t* ah = aHI + 4*kk;
        const uint32_t* al = aLO + 4*kk;
        #pragma unroll
        for (int ntp = 0; ntp < 8; ++ntp) {
            uint32_t off = TR ? (uint32_t)(kk*4352 + ntp*32) : (uint32_t)(ntp*4352 + kk*32);
            uint32_t bh0,bh1,bh2,bh3, bl0,bl1,bl2,bl3;
            if (TR) { LDSM4T(bh0,bh1,bh2,bh3, baseHI + off); LDSM4T(bl0,bl1,bl2,bl3, baseLO + off); }
            else    { LDSM4 (bh0,bh1,bh2,bh3, baseHI + off); LDSM4 (bl0,bl1,bl2,bl3, baseLO + off); }
            float* d0 = d + 8*ntp;
            float* d1 = d0 + 4;
            MMA4(d0, ah, bh0, bh1);
            MMA4(d1, ah, bh2, bh3);
            MMA4(d0, al, bh0, bh1);
            MMA4(d1, al, bh2, bh3);
            MMA4(d0, ah, bl0, bl1);
            MMA4(d1, ah, bl2, bl3);
        }
    }
}

// fwd epilogue: silu -> A hi/lo regs; silu' hi/lo pairs -> global scratch (coalesced)
__device__ __forceinline__ void epi_fwd(const float* d, const float* bias, int tg,
                                        uint32_t* aHI, uint32_t* aLO, uint2* sp)
{
    #pragma unroll
    for (int j = 0; j < 16; ++j) {
        int c0 = 8*j + 2*tg;
        float b0 = bias[c0], b1v = bias[c0+1];
        float h0,s0,h1,s1v,h2,s2v,h3,s3v;
        silu2(d[4*j]   + b0,  &h0, &s0);
        silu2(d[4*j+1] + b1v, &h1, &s1v);
        silu2(d[4*j+2] + b0,  &h2, &s2v);
        silu2(d[4*j+3] + b1v, &h3, &s3v);
        aHI[2*j]   = pack_hl(h0, h1, &aLO[2*j]);
        aHI[2*j+1] = pack_hl(h2, h3, &aLO[2*j+1]);
        sp[(2*j)*NT]   = pack_hl2(s0,  s1v);
        sp[(2*j+1)*NT] = pack_hl2(s2v, s3v);
    }
}
__device__ __forceinline__ void epi_u4(const float* d, const float* b4s, const float* w5s,
                                       int tg, uint32_t* aHI, uint32_t* aLO)
{
    #pragma unroll
    for (int j = 0; j < 16; ++j) {
        int c0 = 8*j + 2*tg;
        float b0 = b4s[c0], b1v = b4s[c0+1];
        float w0 = w5s[c0], w1v = w5s[c0+1];
        float s0 = silu_d(d[4*j]   + b0);
        float s1v = silu_d(d[4*j+1] + b1v);
        float s2v = silu_d(d[4*j+2] + b0);
        float s3v = silu_d(d[4*j+3] + b1v);
        aHI[2*j]   = pack_hl(w0*s0,  w1v*s1v, &aLO[2*j]);
        aHI[2*j+1] = pack_hl(w0*s2v, w1v*s3v, &aLO[2*j+1]);
    }
}
// bwd epilogue: u = D * s (s from global scratch) -> A hi/lo
__device__ __forceinline__ void epi_bwd(const float* d, const uint2* sp,
                                        uint32_t* aHI, uint32_t* aLO)
{
    #pragma unroll
    for (int j = 0; j < 16; ++j) {
        uint2 pa = sp[(2*j)*NT];
        uint2 pb = sp[(2*j+1)*NT];
        float2 sa = unpack_hl(pa.x, pa.y);
        float2 sb = unpack_hl(pb.x, pb.y);
        aHI[2*j]   = pack_hl(d[4*j]*sa.x,   d[4*j+1]*sa.y, &aLO[2*j]);
        aHI[2*j+1] = pack_hl(d[4*j+2]*sb.x, d[4*j+3]*sb.y, &aLO[2*j+1]);
    }
}

__global__ __launch_bounds__(NT, 1)
void ebm_hmma_kernel(
    const float* __restrict__ x0,
    const float* __restrict__ w1, const float* __restrict__ b1,
    const float* __restrict__ w2, const float* __restrict__ b2,
    const float* __restrict__ w3, const float* __restrict__ b3,
    const float* __restrict__ w4, const float* __restrict__ b4,
    const float* __restrict__ w5,
    const float* __restrict__ noise,
    float* __restrict__ out, int nChains, int nSteps)
{
    extern __shared__ char sm[];
    float* w1s  = (float*)(sm + OFF_W1);
    float* b1s  = (float*)(sm + OFF_B1);
    float* b2s  = (float*)(sm + OFF_B2);
    float* b3s  = (float*)(sm + OFF_B3);
    float* b4s  = (float*)(sm + OFF_B4);
    float* w5s  = (float*)(sm + OFF_W5);
    const uint32_t sb = smem_u32(sm);

    const int tid  = threadIdx.x;
    const int lane = tid & 31, warp = tid >> 5;
    const int tg   = lane & 3, g = lane >> 2;
    const int r0   = warp*16 + g, r1 = r0 + 8;

    // per-thread scratch pointers: s2 at slots 0..31, s3 at slots 32..63 (per block)
    uint2* s2p = g_sscr + ((size_t)blockIdx.x * 64) * NT + tid;
    uint2* s3p = s2p + (size_t)32 * NT;

    // per-lane ldmatrix offsets (bytes)
    const uint32_t loF = (uint32_t)(((lane&7) + ((lane>>4)&1)*8)*272 + ((lane>>3)&1)*16);
    const uint32_t loB = (uint32_t)(((lane&7) + ((lane>>3)&1)*8)*272 + ((lane>>4)&1)*16);

    // ---- load weights once per CTA: F[a][b] = W[b][a], hi + lo fp16 ----
    {
        const float* wsrc[3] = {w2, w3, w4};
        #pragma unroll
        for (int m = 0; m < 3; ++m) {
            char* hi = sm + OFF_WHI + m*TILE;
            char* lo = sm + OFF_WLO + m*TILE;
            const float* w = wsrc[m];
            for (int idx = tid; idx < H*H; idx += NT) {
                int k = idx >> 7, j = idx & 127;      // w[k][j]
                float v = w[idx];
                __half h = __float2half_rn(v);
                __half l = __float2half_rn(v - __half2float(h));
                int o = (j*SP + k)*2;                 // F[j][k]
                *(__half*)(hi + o) = h;
                *(__half*)(lo + o) = l;
            }
        }
        if (tid < 2*H) w1s[tid] = w1[tid];
        if (tid < H) {
            b1s[tid] = b1[tid]; b2s[tid] = b2[tid]; b3s[tid] = b3[tid];
            b4s[tid] = b4[tid]; w5s[tid] = w5[tid];
        }
    }
    __syncthreads();

    const uint32_t t0h = sb + OFF_WHI + 0*TILE, t0l = sb + OFF_WLO + 0*TILE;
    const uint32_t t1h = sb + OFF_WHI + 1*TILE, t1l = sb + OFF_WLO + 1*TILE;
    const uint32_t t2h = sb + OFF_WHI + 2*TILE, t2l = sb + OFF_WLO + 2*TILE;

    // ---- anti-phase skew: warps 4-7 (SMSP partners of warps 0-3) burn ~half a
    // step of tensor work once, so partner warps stay in opposite phases and
    // each epilogue overlaps the partner's MMA phase. Results are discarded;
    // the never-true guarded store keeps the MMAs alive against DCE.
    if (warp >= 4) {
        uint32_t aHIw[32], aLOw[32];
        float dd[64];
        #pragma unroll
        for (int i = 0; i < 32; ++i) { aHIw[i] = 0x3C003C00u; aLOw[i] = 0x3C003C00u; }
        do_gemm<false>(dd, aHIw, aLOw, t0h + loF, t0l + loF);
        do_gemm<false>(dd, aHIw, aLOw, t1h + loF, t1l + loF);
        do_gemm<false>(dd, aHIw, aLOw, t2h + loF, t2l + loF);
        if (nSteps < 0) {   // never true at runtime; opaque to the compiler
            float acc = 0.f;
            #pragma unroll
            for (int i = 0; i < 64; ++i) acc += dd[i];
            out[tid] = acc;
        }
    }

    const float2* nz2 = (const float2*)noise;
    const int nTiles = (nChains + CPB - 1) / CPB;

    // ---- persistent loop over chain tiles ----
    for (int tile = blockIdx.x; tile < nTiles; tile += gridDim.x) {
        const int ch0 = tile*CPB + r0, ch1 = tile*CPB + r1;
        float2 xv0 = (ch0 < nChains) ? ((const float2*)x0)[ch0] : make_float2(0.f, 0.f);
        float2 xv1 = (ch1 < nChains) ? ((const float2*)x0)[ch1] : make_float2(0.f, 0.f);

        uint32_t aHI[32], aLO[32];
        float d[64];

        for (int t = 0; t < nSteps; ++t) {
            const float eps = 10.0f * (1.0f - (float)t / (float)nSteps);

            // ---- layer 1 (SIMT): h1 = silu(b1 + x.w1); s1 recomputed later ----
            #pragma unroll
            for (int j = 0; j < 16; ++j) {
                int c0 = 8*j + 2*tg;
                float wa = w1s[c0], wb = w1s[c0+1], wc = w1s[128+c0], wd = w1s[129+c0];
                float ba = b1s[c0], bb = b1s[c0+1];
                float h0,sa0,h1v,sa1,h2,sb0,h3,sb1;
                silu2(ba + xv0.x*wa + xv0.y*wc, &h0,  &sa0);
                silu2(bb + xv0.x*wb + xv0.y*wd, &h1v, &sa1);
                silu2(ba + xv1.x*wa + xv1.y*wc, &h2,  &sb0);
                silu2(bb + xv1.x*wb + xv1.y*wd, &h3,  &sb1);
                aHI[2*j]   = pack_hl(h0, h1v, &aLO[2*j]);
                aHI[2*j+1] = pack_hl(h2, h3,  &aLO[2*j+1]);
            }

            do_gemm<false>(d, aHI, aLO, t0h + loF, t0l + loF);   // z2
            epi_fwd(d, b2s, tg, aHI, aLO, s2p);
            do_gemm<false>(d, aHI, aLO, t1h + loF, t1l + loF);   // z3
            epi_fwd(d, b3s, tg, aHI, aLO, s3p);
            do_gemm<false>(d, aHI, aLO, t2h + loF, t2l + loF);   // z4
            epi_u4(d, b4s, w5s, tg, aHI, aLO);                   // u4 = w5*silu'(z4)
            do_gemm<true>(d, aHI, aLO, t2h + loB, t2l + loB);    // u3 raw
            epi_bwd(d, s3p, aHI, aLO);
            do_gemm<true>(d, aHI, aLO, t1h + loB, t1l + loB);    // u2 raw
            epi_bwd(d, s2p, aHI, aLO);
            do_gemm<true>(d, aHI, aLO, t0h + loB, t0l + loB);    // u1 raw

            // ---- final: recompute s1; u1 = D*s1; g[dim] = sum_k u1[k]*w1[dim][k] ----
            float a00 = 0.f, a01 = 0.f, a10 = 0.f, a11 = 0.f;
            #pragma unroll
            for (int j = 0; j < 16; ++j) {
                int c0 = 8*j + 2*tg;
                float wa = w1s[c0], wb = w1s[c0+1], wc = w1s[128+c0], wd = w1s[129+c0];
                float ba = b1s[c0], bb = b1s[c0+1];
                float sa0 = silu_d(ba + xv0.x*wa + xv0.y*wc);
                float sa1 = silu_d(bb + xv0.x*wb + xv0.y*wd);
                float sb0 = silu_d(ba + xv1.x*wa + xv1.y*wc);
                float sb1 = silu_d(bb + xv1.x*wb + xv1.y*wd);
                float u0 = d[4*j]*sa0,   u1v = d[4*j+1]*sa1;
                float u2 = d[4*j+2]*sb0, u3  = d[4*j+3]*sb1;
                a00 += u0*wa + u1v*wb;  a01 += u0*wc + u1v*wd;
                a10 += u2*wa + u3*wb;   a11 += u2*wc + u3*wd;
            }
            #pragma unroll
            for (int m = 1; m <= 2; m <<= 1) {
                a00 += __shfl_xor_sync(0xffffffffu, a00, m);
                a01 += __shfl_xor_sync(0xffffffffu, a01, m);
                a10 += __shfl_xor_sync(0xffffffffu, a10, m);
                a11 += __shfl_xor_sync(0xffffffffu, a11, m);
            }

            // ---- x update, all 4 lanes redundantly (identical, deterministic) ----
            {
                float g0 = fminf(fmaxf(a00, -0.03f), 0.03f);
                float g1 = fminf(fmaxf(a01, -0.03f), 0.03f);
                float g2 = fminf(fmaxf(a10, -0.03f), 0.03f);
                float g3 = fminf(fmaxf(a11, -0.03f), 0.03f);
                float sq = sqrtf(2.0f * eps);
                float2 nzA = (ch0 < nChains) ? nz2[(size_t)t*nChains + ch0] : make_float2(0.f, 0.f);
                float2 nzB = (ch1 < nChains) ? nz2[(size_t)t*nChains + ch1] : make_float2(0.f, 0.f);
                xv0.x = fminf(fmaxf(xv0.x + sq*nzA.x*0.005f + eps*g0, -2.43f), 3.05f);
                xv0.y = fminf(fmaxf(xv0.y + sq*nzA.y*0.005f + eps*g1, -2.43f), 3.05f);
                xv1.x = fminf(fmaxf(xv1.x + sq*nzB.x*0.005f + eps*g2, -2.43f), 3.05f);
                xv1.y = fminf(fmaxf(xv1.y + sq*nzB.y*0.005f + eps*g3, -2.43f), 3.05f);
            }
        }

        if (tg == 0) {
            if (ch0 < nChains) ((float2*)out)[ch0] = xv0;
            if (ch1 < nChains) ((float2*)out)[ch1] = xv1;
        }
    }
}

extern "C" void kernel_launch(void* const* d_in, const int* in_sizes, int n_in,
                              void* d_out, int out_size) {
    const float* x0 = (const float*)d_in[0];
    const float* w1 = (const float*)d_in[1];
    const float* b1 = (const float*)d_in[2];
    const float* w2 = (const float*)d_in[3];
    const float* b2 = (const float*)d_in[4];
    const float* w3 = (const float*)d_in[5];
    const float* b3 = (const float*)d_in[6];
    const float* w4 = (const float*)d_in[7];
    const float* b4 = (const float*)d_in[8];
    const float* w5 = (const float*)d_in[9];
    // d_in[10] = b5: constant offset, no effect on gradient
    const float* noise = (const float*)d_in[11];
    float* out = (float*)d_out;

    int nChains = in_sizes[0] / 2;
    int nSteps  = in_sizes[11] / in_sizes[0];

    cudaFuncSetAttribute(ebm_hmma_kernel, cudaFuncAttributeMaxDynamicSharedMemorySize, SMEM_BYTES);
    int nTiles = (nChains + CPB - 1) / CPB;
    int grid = (nTiles < NBLK) ? nTiles : NBLK;
    ebm_hmma_kernel<<<grid, NT, SMEM_BYTES>>>(x0, w1, b1, w2, b2, w3, b3, w4, b4, w5,
                                              noise, out, nChains, nSteps);
}

// round 13
// speedup vs baseline: 1.7829x; 1.1945x over previous
#include <cuda_runtime.h>
#include <cuda_fp16.h>
#include <stdint.h>
#include <math.h>

// EBM Langevin MCMC via mma.sync HMMA. R12: NT=384 (3 warps/SMSP) — retest of
// R7's occupancy raise, now with the two proven guards: VOLATILE ldmatrix
// (both guard trips R7/R8 had non-volatile LDSM -> loop-invariant hoisting ->
// 1.6GB local demotion; volatile pins weight loads in-loop) and s2/s3 in a
// small __device__ global scratch (R9). Staggered warm-up skew per warp-quad
// (R11's +1% win generalized to 3-way).
// Weights: one SMEM tile per layer, F[a][b] = W[b][a] fp16 hi+lo, pad-136 rows.
//   fwd GEMM:  B[k][n] = F[n][k]  -> ldmatrix (non-trans)
//   bwd GEMM:  B[j][n] = F[j][n]  -> ldmatrix.trans  (same tile)
// 3-pass per GEMM: Ahi*Bhi + Alo*Bhi + Ahi*Blo => ~fp32 accuracy.

#define H 128
#define NT 384
#define CPB 192                // chains per CTA (12 warps * 16)
#define SP 136                 // padded row stride (halves); 272 bytes
#define TILE 34816             // 128*272 bytes
#define NBLK 152               // persistent grid size (>= SM count)

#define OFF_WHI 0
#define OFF_WLO (3*TILE)       // 104448
#define OFF_W1  208896
#define OFF_B1  209920
#define OFF_B2  210432
#define OFF_B3  210944
#define OFF_B4  211456
#define OFF_W5  211968
#define SMEM_BYTES 212480

// scratch for s2/s3: [block][64 slots][384 threads] uint2 = ~30 MB total
__device__ uint2 g_sscr[(size_t)NBLK * 64 * NT];

// non-volatile: pure register computation, lets compiler interleave chains
#define MMA4(D, A, b0, b1) asm( \
  "mma.sync.aligned.m16n8k16.row.col.f32.f16.f16.f32 " \
  "{%0,%1,%2,%3},{%4,%5,%6,%7},{%8,%9},{%0,%1,%2,%3};" \
  : "+f"((D)[0]),"+f"((D)[1]),"+f"((D)[2]),"+f"((D)[3]) \
  : "r"((A)[0]),"r"((A)[1]),"r"((A)[2]),"r"((A)[3]),"r"(b0),"r"(b1))

// write-only D with C = 0 (no accumulator init needed)
#define MMA4Z(D, A, b0, b1) asm( \
  "mma.sync.aligned.m16n8k16.row.col.f32.f16.f16.f32 " \
  "{%0,%1,%2,%3},{%4,%5,%6,%7},{%8,%9},{%10,%10,%10,%10};" \
  : "=f"((D)[0]),"=f"((D)[1]),"=f"((D)[2]),"=f"((D)[3]) \
  : "r"((A)[0]),"r"((A)[1]),"r"((A)[2]),"r"((A)[3]),"r"(b0),"r"(b1),"f"(0.0f))

// VOLATILE: keeps ldmatrix inside the step loop (prevents invariant hoisting
// of the whole weight tile into local memory — the R7/R8 guard-trip cause)
#define LDSM4(r0,r1,r2,r3,a) asm volatile( \
  "ldmatrix.sync.aligned.m8n8.x4.shared.b16 {%0,%1,%2,%3}, [%4];" \
  : "=r"(r0),"=r"(r1),"=r"(r2),"=r"(r3) : "r"(a))

#define LDSM4T(r0,r1,r2,r3,a) asm volatile( \
  "ldmatrix.sync.aligned.m8n8.x4.trans.shared.b16 {%0,%1,%2,%3}, [%4];" \
  : "=r"(r0),"=r"(r1),"=r"(r2),"=r"(r3) : "r"(a))

__device__ __forceinline__ uint32_t smem_u32(const void* p) {
    uint32_t a;
    asm("{ .reg .u64 t; cvta.to.shared.u64 t, %1; cvt.u32.u64 %0, t; }" : "=r"(a) : "l"(p));
    return a;
}
__device__ __forceinline__ void silu2(float z, float* h, float* sp) {
    float sg = __fdividef(1.0f, 1.0f + __expf(-z));
    *h = z * sg;
    *sp = sg * (1.0f + z * (1.0f - sg));
}
__device__ __forceinline__ float silu_d(float z) {
    float sg = __fdividef(1.0f, 1.0f + __expf(-z));
    return sg * (1.0f + z * (1.0f - sg));
}
__device__ __forceinline__ uint32_t pack_hl(float v0, float v1, uint32_t* lo) {
    __half h0 = __float2half_rn(v0), h1 = __float2half_rn(v1);
    __half l0 = __float2half_rn(v0 - __half2float(h0));
    __half l1 = __float2half_rn(v1 - __half2float(h1));
    __half2 hp = __halves2half2(h0, h1), lp = __halves2half2(l0, l1);
    *lo = *reinterpret_cast<uint32_t*>(&lp);
    return *reinterpret_cast<uint32_t*>(&hp);
}
__device__ __forceinline__ uint2 pack_hl2(float v0, float v1) {
    uint2 r;
    r.x = pack_hl(v0, v1, &r.y);
    return r;
}
__device__ __forceinline__ float2 unpack2(uint32_t u) {
    return __half22float2(*reinterpret_cast<__half2*>(&u));
}
__device__ __forceinline__ float2 unpack_hl(uint32_t hi, uint32_t lo) {
    float2 a = unpack2(hi), b = unpack2(lo);
    return make_float2(a.x + b.x, a.y + b.y);
}

// fwd (TR=false): addr = base + ntp*4352 + kk*32 ; bwd (TR=true): base + kk*4352 + ntp*32
template<bool TR>
__device__ __forceinline__ void do_gemm(float* d, const uint32_t* aHI, const uint32_t* aLO,
                                        uint32_t baseHI, uint32_t baseLO)
{
    // kk = 0: zero-C MMAs initialize d
    {
        const uint32_t* ah = aHI;
        const uint32_t* al = aLO;
        #pragma unroll
        for (int ntp = 0; ntp < 8; ++ntp) {
            uint32_t off = TR ? (uint32_t)(ntp*32) : (uint32_t)(ntp*4352);
            uint32_t bh0,bh1,bh2,bh3, bl0,bl1,bl2,bl3;
            if (TR) { LDSM4T(bh0,bh1,bh2,bh3, baseHI + off); LDSM4T(bl0,bl1,bl2,bl3, baseLO + off); }
            else    { LDSM4 (bh0,bh1,bh2,bh3, baseHI + off); LDSM4 (bl0,bl1,bl2,bl3, baseLO + off); }
            float* d0 = d + 8*ntp;
            float* d1 = d0 + 4;
            MMA4Z(d0, ah, bh0, bh1);
            MMA4Z(d1, ah, bh2, bh3);
            MMA4(d0, al, bh0, bh1);
            MMA4(d1, al, bh2, bh3);
            MMA4(d0, ah, bl0, bl1);
            MMA4(d1, ah, bl2, bl3);
        }
    }
    #pragma unroll
    for (int kk = 1; kk < 8; ++kk) {
        const uint32_t* ah = aHI + 4*kk;
        const uint32_t* al = aLO + 4*kk;
        #pragma unroll
        for (int ntp = 0; ntp < 8; ++ntp) {
            uint32_t off = TR ? (uint32_t)(kk*4352 + ntp*32) : (uint32_t)(ntp*4352 + kk*32);
            uint32_t bh0,bh1,bh2,bh3, bl0,bl1,bl2,bl3;
            if (TR) { LDSM4T(bh0,bh1,bh2,bh3, baseHI + off); LDSM4T(bl0,bl1,bl2,bl3, baseLO + off); }
            else    { LDSM4 (bh0,bh1,bh2,bh3, baseHI + off); LDSM4 (bl0,bl1,bl2,bl3, baseLO + off); }
            float* d0 = d + 8*ntp;
            float* d1 = d0 + 4;
            MMA4(d0, ah, bh0, bh1);
            MMA4(d1, ah, bh2, bh3);
            MMA4(d0, al, bh0, bh1);
            MMA4(d1, al, bh2, bh3);
            MMA4(d0, ah, bl0, bl1);
            MMA4(d1, ah, bl2, bl3);
        }
    }
}

// fwd epilogue: silu -> A hi/lo regs; silu' hi/lo pairs -> global scratch (coalesced)
__device__ __forceinline__ void epi_fwd(const float* d, const float* bias, int tg,
                                        uint32_t* aHI, uint32_t* aLO, uint2* sp)
{
    #pragma unroll
    for (int j = 0; j < 16; ++j) {
        int c0 = 8*j + 2*tg;
        float b0 = bias[c0], b1v = bias[c0+1];
        float h0,s0,h1,s1v,h2,s2v,h3,s3v;
        silu2(d[4*j]   + b0,  &h0, &s0);
        silu2(d[4*j+1] + b1v, &h1, &s1v);
        silu2(d[4*j+2] + b0,  &h2, &s2v);
        silu2(d[4*j+3] + b1v, &h3, &s3v);
        aHI[2*j]   = pack_hl(h0, h1, &aLO[2*j]);
        aHI[2*j+1] = pack_hl(h2, h3, &aLO[2*j+1]);
        sp[(2*j)*NT]   = pack_hl2(s0,  s1v);
        sp[(2*j+1)*NT] = pack_hl2(s2v, s3v);
    }
}
__device__ __forceinline__ void epi_u4(const float* d, const float* b4s, const float* w5s,
                                       int tg, uint32_t* aHI, uint32_t* aLO)
{
    #pragma unroll
    for (int j = 0; j < 16; ++j) {
        int c0 = 8*j + 2*tg;
        float b0 = b4s[c0], b1v = b4s[c0+1];
        float w0 = w5s[c0], w1v = w5s[c0+1];
        float s0 = silu_d(d[4*j]   + b0);
        float s1v = silu_d(d[4*j+1] + b1v);
        float s2v = silu_d(d[4*j+2] + b0);
        float s3v = silu_d(d[4*j+3] + b1v);
        aHI[2*j]   = pack_hl(w0*s0,  w1v*s1v, &aLO[2*j]);
        aHI[2*j+1] = pack_hl(w0*s2v, w1v*s3v, &aLO[2*j+1]);
    }
}
// bwd epilogue: u = D * s (s from global scratch) -> A hi/lo
__device__ __forceinline__ void epi_bwd(const float* d, const uint2* sp,
                                        uint32_t* aHI, uint32_t* aLO)
{
    #pragma unroll
    for (int j = 0; j < 16; ++j) {
        uint2 pa = sp[(2*j)*NT];
        uint2 pb = sp[(2*j+1)*NT];
        float2 sa = unpack_hl(pa.x, pa.y);
        float2 sb = unpack_hl(pb.x, pb.y);
        aHI[2*j]   = pack_hl(d[4*j]*sa.x,   d[4*j+1]*sa.y, &aLO[2*j]);
        aHI[2*j+1] = pack_hl(d[4*j+2]*sb.x, d[4*j+3]*sb.y, &aLO[2*j+1]);
    }
}

__global__ __launch_bounds__(NT, 1)
void ebm_hmma_kernel(
    const float* __restrict__ x0,
    const float* __restrict__ w1, const float* __restrict__ b1,
    const float* __restrict__ w2, const float* __restrict__ b2,
    const float* __restrict__ w3, const float* __restrict__ b3,
    const float* __restrict__ w4, const float* __restrict__ b4,
    const float* __restrict__ w5,
    const float* __restrict__ noise,
    float* __restrict__ out, int nChains, int nSteps)
{
    extern __shared__ char sm[];
    float* w1s  = (float*)(sm + OFF_W1);
    float* b1s  = (float*)(sm + OFF_B1);
    float* b2s  = (float*)(sm + OFF_B2);
    float* b3s  = (float*)(sm + OFF_B3);
    float* b4s  = (float*)(sm + OFF_B4);
    float* w5s  = (float*)(sm + OFF_W5);
    const uint32_t sb = smem_u32(sm);

    const int tid  = threadIdx.x;
    const int lane = tid & 31, warp = tid >> 5;
    const int tg   = lane & 3, g = lane >> 2;
    const int r0   = warp*16 + g, r1 = r0 + 8;

    // per-thread scratch pointers: s2 at slots 0..31, s3 at slots 32..63 (per block)
    uint2* s2p = g_sscr + ((size_t)blockIdx.x * 64) * NT + tid;
    uint2* s3p = s2p + (size_t)32 * NT;

    // per-lane ldmatrix offsets (bytes)
    const uint32_t loF = (uint32_t)(((lane&7) + ((lane>>4)&1)*8)*272 + ((lane>>3)&1)*16);
    const uint32_t loB = (uint32_t)(((lane&7) + ((lane>>3)&1)*8)*272 + ((lane>>4)&1)*16);

    // ---- load weights once per CTA: F[a][b] = W[b][a], hi + lo fp16 ----
    {
        const float* wsrc[3] = {w2, w3, w4};
        #pragma unroll
        for (int m = 0; m < 3; ++m) {
            char* hi = sm + OFF_WHI + m*TILE;
            char* lo = sm + OFF_WLO + m*TILE;
            const float* w = wsrc[m];
            for (int idx = tid; idx < H*H; idx += NT) {
                int k = idx >> 7, j = idx & 127;      // w[k][j]
                float v = w[idx];
                __half h = __float2half_rn(v);
                __half l = __float2half_rn(v - __half2float(h));
                int o = (j*SP + k)*2;                 // F[j][k]
                *(__half*)(hi + o) = h;
                *(__half*)(lo + o) = l;
            }
        }
        if (tid < 2*H) w1s[tid] = w1[tid];
        if (tid < H) {
            b1s[tid] = b1[tid]; b2s[tid] = b2[tid]; b3s[tid] = b3[tid];
            b4s[tid] = b4[tid]; w5s[tid] = w5[tid];
        }
    }
    __syncthreads();

    const uint32_t t0h = sb + OFF_WHI + 0*TILE, t0l = sb + OFF_WLO + 0*TILE;
    const uint32_t t1h = sb + OFF_WHI + 1*TILE, t1l = sb + OFF_WLO + 1*TILE;
    const uint32_t t2h = sb + OFF_WHI + 2*TILE, t2l = sb + OFF_WLO + 2*TILE;

    // ---- anti-phase skew: warp-quad q in {0,1,2} burns 2q dummy GEMMs once,
    // spreading the 3 warps per SMSP across step phases (R11 pattern, 3-way).
    {
        const int nskew = 2 * (warp >> 2);   // 0, 2, 4
        if (nskew > 0) {
            uint32_t aHIw[32], aLOw[32];
            float dd[64];
            #pragma unroll
            for (int i = 0; i < 32; ++i) { aHIw[i] = 0x3C003C00u; aLOw[i] = 0x3C003C00u; }
            for (int q = 0; q < nskew; ++q) {
                do_gemm<false>(dd, aHIw, aLOw,
                               ((q & 1) ? t1h : t0h) + loF,
                               ((q & 1) ? t1l : t0l) + loF);
            }
            if (nSteps < 0) {   // never true at runtime; opaque to the compiler
                float acc = 0.f;
                #pragma unroll
                for (int i = 0; i < 64; ++i) acc += dd[i];
                out[tid] = acc;
            }
        }
    }

    const float2* nz2 = (const float2*)noise;
    const int nTiles = (nChains + CPB - 1) / CPB;

    // ---- persistent loop over chain tiles ----
    for (int tile = blockIdx.x; tile < nTiles; tile += gridDim.x) {
        const int ch0 = tile*CPB + r0, ch1 = tile*CPB + r1;
        float2 xv0 = (ch0 < nChains) ? ((const float2*)x0)[ch0] : make_float2(0.f, 0.f);
        float2 xv1 = (ch1 < nChains) ? ((const float2*)x0)[ch1] : make_float2(0.f, 0.f);

        uint32_t aHI[32], aLO[32];
        float d[64];

        for (int t = 0; t < nSteps; ++t) {
            const float eps = 10.0f * (1.0f - (float)t / (float)nSteps);

            // ---- layer 1 (SIMT): h1 = silu(b1 + x.w1); s1 recomputed later ----
            #pragma unroll
            for (int j = 0; j < 16; ++j) {
                int c0 = 8*j + 2*tg;
                float wa = w1s[c0], wb = w1s[c0+1], wc = w1s[128+c0], wd = w1s[129+c0];
                float ba = b1s[c0], bb = b1s[c0+1];
                float h0,sa0,h1v,sa1,h2,sb0,h3,sb1;
                silu2(ba + xv0.x*wa + xv0.y*wc, &h0,  &sa0);
                silu2(bb + xv0.x*wb + xv0.y*wd, &h1v, &sa1);
                silu2(ba + xv1.x*wa + xv1.y*wc, &h2,  &sb0);
                silu2(bb + xv1.x*wb + xv1.y*wd, &h3,  &sb1);
                aHI[2*j]   = pack_hl(h0, h1v, &aLO[2*j]);
                aHI[2*j+1] = pack_hl(h2, h3,  &aLO[2*j+1]);
            }

            do_gemm<false>(d, aHI, aLO, t0h + loF, t0l + loF);   // z2
            epi_fwd(d, b2s, tg, aHI, aLO, s2p);
            do_gemm<false>(d, aHI, aLO, t1h + loF, t1l + loF);   // z3
            epi_fwd(d, b3s, tg, aHI, aLO, s3p);
            do_gemm<false>(d, aHI, aLO, t2h + loF, t2l + loF);   // z4
            epi_u4(d, b4s, w5s, tg, aHI, aLO);                   // u4 = w5*silu'(z4)
            do_gemm<true>(d, aHI, aLO, t2h + loB, t2l + loB);    // u3 raw
            epi_bwd(d, s3p, aHI, aLO);
            do_gemm<true>(d, aHI, aLO, t1h + loB, t1l + loB);    // u2 raw
            epi_bwd(d, s2p, aHI, aLO);
            do_gemm<true>(d, aHI, aLO, t0h + loB, t0l + loB);    // u1 raw

            // ---- final: recompute s1; u1 = D*s1; g[dim] = sum_k u1[k]*w1[dim][k] ----
            float a00 = 0.f, a01 = 0.f, a10 = 0.f, a11 = 0.f;
            #pragma unroll
            for (int j = 0; j < 16; ++j) {
                int c0 = 8*j + 2*tg;
                float wa = w1s[c0], wb = w1s[c0+1], wc = w1s[128+c0], wd = w1s[129+c0];
                float ba = b1s[c0], bb = b1s[c0+1];
                float sa0 = silu_d(ba + xv0.x*wa + xv0.y*wc);
                float sa1 = silu_d(bb + xv0.x*wb + xv0.y*wd);
                float sb0 = silu_d(ba + xv1.x*wa + xv1.y*wc);
                float sb1 = silu_d(bb + xv1.x*wb + xv1.y*wd);
                float u0 = d[4*j]*sa0,   u1v = d[4*j+1]*sa1;
                float u2 = d[4*j+2]*sb0, u3  = d[4*j+3]*sb1;
                a00 += u0*wa + u1v*wb;  a01 += u0*wc + u1v*wd;
                a10 += u2*wa + u3*wb;   a11 += u2*wc + u3*wd;
            }
            #pragma unroll
            for (int m = 1; m <= 2; m <<= 1) {
                a00 += __shfl_xor_sync(0xffffffffu, a00, m);
                a01 += __shfl_xor_sync(0xffffffffu, a01, m);
                a10 += __shfl_xor_sync(0xffffffffu, a10, m);
                a11 += __shfl_xor_sync(0xffffffffu, a11, m);
            }

            // ---- x update, all 4 lanes redundantly (identical, deterministic) ----
            {
                float g0 = fminf(fmaxf(a00, -0.03f), 0.03f);
                float g1 = fminf(fmaxf(a01, -0.03f), 0.03f);
                float g2 = fminf(fmaxf(a10, -0.03f), 0.03f);
                float g3 = fminf(fmaxf(a11, -0.03f), 0.03f);
                float sq = sqrtf(2.0f * eps);
                float2 nzA = (ch0 < nChains) ? nz2[(size_t)t*nChains + ch0] : make_float2(0.f, 0.f);
                float2 nzB = (ch1 < nChains) ? nz2[(size_t)t*nChains + ch1] : make_float2(0.f, 0.f);
                xv0.x = fminf(fmaxf(xv0.x + sq*nzA.x*0.005f + eps*g0, -2.43f), 3.05f);
                xv0.y = fminf(fmaxf(xv0.y + sq*nzA.y*0.005f + eps*g1, -2.43f), 3.05f);
                xv1.x = fminf(fmaxf(xv1.x + sq*nzB.x*0.005f + eps*g2, -2.43f), 3.05f);
                xv1.y = fminf(fmaxf(xv1.y + sq*nzB.y*0.005f + eps*g3, -2.43f), 3.05f);
            }
        }

        if (tg == 0) {
            if (ch0 < nChains) ((float2*)out)[ch0] = xv0;
            if (ch1 < nChains) ((float2*)out)[ch1] = xv1;
        }
    }
}

extern "C" void kernel_launch(void* const* d_in, const int* in_sizes, int n_in,
                              void* d_out, int out_size) {
    const float* x0 = (const float*)d_in[0];
    const float* w1 = (const float*)d_in[1];
    const float* b1 = (const float*)d_in[2];
    const float* w2 = (const float*)d_in[3];
    const float* b2 = (const float*)d_in[4];
    const float* w3 = (const float*)d_in[5];
    const float* b3 = (const float*)d_in[6];
    const float* w4 = (const float*)d_in[7];
    const float* b4 = (const float*)d_in[8];
    const float* w5 = (const float*)d_in[9];
    // d_in[10] = b5: constant offset, no effect on gradient
    const float* noise = (const float*)d_in[11];
    float* out = (float*)d_out;

    int nChains = in_sizes[0] / 2;
    int nSteps  = in_sizes[11] / in_sizes[0];

    cudaFuncSetAttribute(ebm_hmma_kernel, cudaFuncAttributeMaxDynamicSharedMemorySize, SMEM_BYTES);
    int nTiles = (nChains + CPB - 1) / CPB;
    int grid = (nTiles < NBLK) ? nTiles : NBLK;
    ebm_hmma_kernel<<<grid, NT, SMEM_BYTES>>>(x0, w1, b1, w2, b2, w3, b3, w4, b4, w5,
                                              noise, out, nChains, nSteps);
}